// round 5
// baseline (speedup 1.0000x reference)
#include <cuda_runtime.h>

// ---------------- problem constants ----------------
#define WS     12
#define NTOK   144            // WS*WS tokens per window
#define CH     192
#define NHEADS 6
#define HD     32
#define IMG    256
#define NWH    22             // windows per side (264/12)
#define NB     4
#define NWIN   (NB*NWH*NWH)   // 1936
#define PSTR   160            // x_s pair-layout stride: 8 ty-groups * 20 floats
#define ESTR   161            // epilogue staging stride (odd -> bank-safe)
#define QSTR   36             // q/k/v row stride (float4-aligned)
#define AOSTR  160            // attn-out pair-layout channel stride
#define SCALE  0.17677669529663687f   // 32^-0.5

typedef unsigned long long u64;

__device__ __forceinline__ u64 dup2(float v) {
    u64 r; asm("mov.b64 %0, {%1, %1};" : "=l"(r) : "f"(v)); return r;
}
__device__ __forceinline__ void fma2(u64& d, u64 a, u64 b) {
    asm("fma.rn.f32x2 %0, %1, %2, %0;" : "+l"(d) : "l"(a), "l"(b));
}
__device__ __forceinline__ void unpack2(u64 v, float& lo, float& hi) {
    asm("mov.b64 {%0, %1}, %2;" : "=f"(lo), "=f"(hi) : "l"(v));
}
__device__ __forceinline__ float f4e(const float4& f, int i) {
    return i == 0 ? f.x : (i == 1 ? f.y : (i == 2 ? f.z : f.w));
}
// pair layout: n = p*16 + which*8 + ty  ->  col = ty*20 + p*2 + which
__device__ __forceinline__ int paircol(int n) {
    return (n & 7) * 20 + (n >> 4) * 2 + ((n >> 3) & 1);
}

// load 9 contiguous row-pairs (18 floats) as 4x LDS.128 + 1x LDS.64
__device__ __forceinline__ void load_pairs(const float* base, u64* xa) {
    float4 v0 = *(const float4*)(base);
    float4 v1 = *(const float4*)(base + 4);
    float4 v2 = *(const float4*)(base + 8);
    float4 v3 = *(const float4*)(base + 12);
    u64    v4 = *(const u64*)(base + 16);
    xa[0] = ((const u64*)&v0)[0]; xa[1] = ((const u64*)&v0)[1];
    xa[2] = ((const u64*)&v1)[0]; xa[3] = ((const u64*)&v1)[1];
    xa[4] = ((const u64*)&v2)[0]; xa[5] = ((const u64*)&v2)[1];
    xa[6] = ((const u64*)&v3)[0]; xa[7] = ((const u64*)&v3)[1];
    xa[8] = v4;
}

// =====================================================================
// Fully fused kernel: one block per window, 256 threads.
// =====================================================================
__global__ void __launch_bounds__(256, 1)
wsa_fused(const float* __restrict__ x, const float* __restrict__ wqkv,
          const float* __restrict__ wproj, float* __restrict__ out) {
    extern __shared__ float smem[];
    float* x_s = smem;                       // CH*ESTR slab; GEMM phase uses stride PSTR
    float* q_s = smem + CH * ESTR;           // 144*36 (reused as ao_s)
    float* k_s = q_s + NTOK * QSTR;
    float* v_s = k_s + NTOK * QSTR;
    float* ao_s = q_s;                       // [32][AOSTR] attn-out pair layout

    const int win = blockIdx.x;
    const int b   = win / (NWH * NWH);
    const int r0  = win % (NWH * NWH);
    const int wh  = r0 / NWH, ww = r0 % NWH;
    const int tid = threadIdx.x;

    // ---- stage window: reflect pad, pair-interleaved layout ----
    const float* xb = x + (size_t)b * CH * IMG * IMG;
    for (int idx = tid; idx < NTOK * CH; idx += 256) {
        int c = idx / NTOK, n = idx % NTOK;
        int i = n / WS, j = n % WS;
        int ph = wh * WS + i; if (ph >= IMG) ph = 2 * IMG - 2 - ph;
        int pw = ww * WS + j; if (pw >= IMG) pw = 2 * IMG - 2 - pw;
        x_s[c * PSTR + paircol(n)] = xb[(c * IMG + ph) * IMG + pw];
    }

    const int ty = tid >> 5;   // 0..7 : row-pair group
    const int tx = tid & 31;   // 0..31: output column within 32-group

    u64 acc[9][6];             // persistent proj accumulators
    #pragma unroll
    for (int p = 0; p < 9; ++p)
        #pragma unroll
        for (int s = 0; s < 6; ++s) acc[p][s] = 0ULL;

    __syncthreads();

    for (int h = 0; h < NHEADS; ++h) {
        // ---------- QKV GEMM: out[144][3*32], K=192, prefetched weights ----------
        const float* wq = wqkv + (size_t)(h * HD + tx) * CH;
        const float* wk = wq + 192 * CH;
        const float* wv = wk + 192 * CH;
        u64 aq[9], ak[9], av[9];
        #pragma unroll
        for (int p = 0; p < 9; ++p) { aq[p] = 0ULL; ak[p] = 0ULL; av[p] = 0ULL; }

        float4 fq = *(const float4*)(wq);
        float4 fk = *(const float4*)(wk);
        float4 fv = *(const float4*)(wv);
        #pragma unroll 1
        for (int c0 = 0; c0 < CH; c0 += 4) {
            int c1 = c0 + 4; if (c1 == CH) c1 = 0;     // wrap: harmless dummy prefetch
            float4 nq = *(const float4*)(wq + c1);
            float4 nk = *(const float4*)(wk + c1);
            float4 nv = *(const float4*)(wv + c1);
            #pragma unroll
            for (int cc = 0; cc < 4; ++cc) {
                u64 bq = dup2(f4e(fq, cc));
                u64 bk = dup2(f4e(fk, cc));
                u64 bv = dup2(f4e(fv, cc));
                u64 xa[9];
                load_pairs(x_s + (c0 + cc) * PSTR + ty * 20, xa);
                #pragma unroll
                for (int p = 0; p < 9; ++p) {
                    fma2(aq[p], xa[p], bq);
                    fma2(ak[p], xa[p], bk);
                    fma2(av[p], xa[p], bv);
                }
            }
            fq = nq; fk = nk; fv = nv;
        }
        #pragma unroll
        for (int p = 0; p < 9; ++p) {
            int n0 = ty + 16 * p, n1 = n0 + 8;
            float l, hh;
            unpack2(aq[p], l, hh); q_s[n0 * QSTR + tx] = l; q_s[n1 * QSTR + tx] = hh;
            unpack2(ak[p], l, hh); k_s[n0 * QSTR + tx] = l; k_s[n1 * QSTR + tx] = hh;
            unpack2(av[p], l, hh); v_s[n0 * QSTR + tx] = l; v_s[n1 * QSTR + tx] = hh;
        }
        __syncthreads();

        // ---------- dilated coset attention (15 keys/query) ----------
        float e[16]; float inv = 0.f;
        int km[16];
        if (tid < NTOK) {
            const int qi = tid / WS, qj = tid % WS;
            const int ca = qi % 3, cb = qj % 3;
            // phase 1: scores (q live only here)
            {
                float4 q4[8];
                #pragma unroll
                for (int d4 = 0; d4 < 8; ++d4)
                    q4[d4] = *(const float4*)(q_s + tid * QSTR + d4 * 4);
                float mx = -1e30f;
                #pragma unroll
                for (int u = 0; u < 4; ++u)
                    #pragma unroll
                    for (int v = 0; v < 4; ++v) {
                        int m = (ca + 3 * u) * WS + (cb + 3 * v);
                        km[u * 4 + v] = m;
                        float sx = 0.f, sy = 0.f, sz = 0.f, sw = 0.f;
                        #pragma unroll
                        for (int d4 = 0; d4 < 8; ++d4) {
                            float4 kk = *(const float4*)(k_s + m * QSTR + d4 * 4);
                            sx += q4[d4].x * kk.x; sy += q4[d4].y * kk.y;
                            sz += q4[d4].z * kk.z; sw += q4[d4].w * kk.w;
                        }
                        float s = ((sx + sy) + (sz + sw)) * SCALE;
                        if (m == tid) s = -1e30f;   // self excluded
                        e[u * 4 + v] = s;
                        mx = fmaxf(mx, s);
                    }
                float den = 0.f;
                #pragma unroll
                for (int t = 0; t < 16; ++t) { e[t] = __expf(e[t] - mx); den += e[t]; }
                inv = 1.0f / den;
            }
        }
        __syncthreads();   // all q_s reads done before ao overwrite

        if (tid < NTOK) {
            const int col = paircol(tid);
            // phase 2: output in two halves of 16 dims (lower register pressure)
            #pragma unroll
            for (int half = 0; half < 2; ++half) {
                float4 o4[4];
                #pragma unroll
                for (int d4 = 0; d4 < 4; ++d4) o4[d4] = make_float4(0.f, 0.f, 0.f, 0.f);
                #pragma unroll
                for (int t = 0; t < 16; ++t) {
                    int m = km[t];
                    float p = e[t];
                    #pragma unroll
                    for (int d4 = 0; d4 < 4; ++d4) {
                        float4 vv = *(const float4*)(v_s + m * QSTR + half * 16 + d4 * 4);
                        o4[d4].x += p * vv.x; o4[d4].y += p * vv.y;
                        o4[d4].z += p * vv.z; o4[d4].w += p * vv.w;
                    }
                }
                #pragma unroll
                for (int d4 = 0; d4 < 4; ++d4) {
                    int dbase = half * 16 + d4 * 4;
                    ao_s[(dbase + 0) * AOSTR + col] = o4[d4].x * inv;
                    ao_s[(dbase + 1) * AOSTR + col] = o4[d4].y * inv;
                    ao_s[(dbase + 2) * AOSTR + col] = o4[d4].z * inv;
                    ao_s[(dbase + 3) * AOSTR + col] = o4[d4].w * inv;
                }
            }
        }
        __syncthreads();

        // ---------- partial proj GEMM: acc += attn_h[144x32] @ Wp_h[:,h*32:+32]^T ----------
        const float* wp = wproj + (size_t)h * HD;
        float4 cw[6];
        #pragma unroll
        for (int s = 0; s < 6; ++s) cw[s] = *(const float4*)(wp + (size_t)(tx + 32 * s) * CH);
        #pragma unroll 1
        for (int c0 = 0; c0 < HD; c0 += 4) {
            int c1 = c0 + 4; if (c1 == HD) c1 = 0;
            float4 nw[6];
            #pragma unroll
            for (int s = 0; s < 6; ++s)
                nw[s] = *(const float4*)(wp + (size_t)(tx + 32 * s) * CH + c1);
            #pragma unroll
            for (int cc = 0; cc < 4; ++cc) {
                u64 xa[9];
                load_pairs(ao_s + (c0 + cc) * AOSTR + ty * 20, xa);
                #pragma unroll
                for (int s = 0; s < 6; ++s) {
                    u64 bw = dup2(f4e(cw[s], cc));
                    #pragma unroll
                    for (int p = 0; p < 9; ++p) fma2(acc[p][s], xa[p], bw);
                }
            }
            #pragma unroll
            for (int s = 0; s < 6; ++s) cw[s] = nw[s];
        }
        __syncthreads();   // proj reads of ao_s done before next head's qkv writes
    }

    // ---------- epilogue: stage channel-major (stride ESTR), scatter with crop ----------
    #pragma unroll
    for (int p = 0; p < 9; ++p) {
        int n0 = ty + 16 * p, n1 = n0 + 8;
        #pragma unroll
        for (int s = 0; s < 6; ++s) {
            float l, hh; unpack2(acc[p][s], l, hh);
            x_s[(tx + 32 * s) * ESTR + n0] = l;
            x_s[(tx + 32 * s) * ESTR + n1] = hh;
        }
    }
    __syncthreads();

    const int hbase = wh * WS, wbase = ww * WS;
    for (int idx = tid; idx < NTOK * CH; idx += 256) {
        int c = idx / NTOK, n = idx % NTOK;
        int i = n / WS, j = n % WS;
        int hh2 = hbase + i, w2 = wbase + j;
        if (hh2 < IMG && w2 < IMG)
            out[(((size_t)b * CH + c) * IMG + hh2) * IMG + w2] = x_s[c * ESTR + n];
    }
}

// =====================================================================
// launch
// =====================================================================
extern "C" void kernel_launch(void* const* d_in, const int* in_sizes, int n_in,
                              void* d_out, int out_size) {
    (void)in_sizes; (void)n_in; (void)out_size;
    const float* x     = (const float*)d_in[0];
    const float* wqkv  = (const float*)d_in[1];
    const float* wproj = (const float*)d_in[2];
    float* out = (float*)d_out;

    const int smemA = (CH * ESTR + 3 * NTOK * QSTR) * (int)sizeof(float); // 185,856 B
    cudaFuncSetAttribute(wsa_fused, cudaFuncAttributeMaxDynamicSharedMemorySize, smemA);
    wsa_fused<<<NWIN, 256, smemA>>>(x, wqkv, wproj, out);
}